// round 1
// baseline (speedup 1.0000x reference)
#include <cuda_runtime.h>
#include <math.h>

// ---------------------------------------------------------------------------
// MultiHeadAttention: B=1, S=4096, D_MODEL=1024, H=16, d_k=64, fp32.
//   Q = q @ Wq^T + bq ; K,V likewise   (stored head-major [H][S][64])
//   attn = softmax(Q K^T / 8) V        (flash-attention tiles 64x64)
//   out  = attn @ Wo^T + bo
// ---------------------------------------------------------------------------

#define S_LEN 4096
#define DMODEL 1024
#define NHEAD 16
#define DK 64

#define BM 128
#define BN 128
#define BK 16

// scratch (allocation-free rule: __device__ globals)
__device__ float g_Q[NHEAD * S_LEN * DK];
__device__ float g_K[NHEAD * S_LEN * DK];
__device__ float g_V[NHEAD * S_LEN * DK];
__device__ float g_attn[S_LEN * DMODEL];

// ---------------------------------------------------------------------------
// GEMM body: Y[m,n] = sum_k X[m,k] * W[n,k] + bias[n]
// M=4096, N=1024, K=1024. Block tile 128x128, K-tile 16, 256 threads,
// 8x8 per thread (columns strided by 16 for conflict-free SMEM reads).
// scatter: write into head-major layout dst[((n>>6)*S + m)*64 + (n&63)].
// ---------------------------------------------------------------------------
__device__ __forceinline__ void gemm_body(
    const float* __restrict__ X, const float* __restrict__ W,
    const float* __restrict__ bias, float* __restrict__ Y, bool scatter)
{
    __shared__ float As[BK][BM + 4];
    __shared__ float Bs[BK][BN + 4];

    const int tid = threadIdx.x;
    const int tr = tid >> 4;      // 0..15 -> output rows tr*8..tr*8+7
    const int tc = tid & 15;      // 0..15 -> output cols tc + 16*u
    const int m0 = blockIdx.y * BM;
    const int n0 = blockIdx.x * BN;

    float acc[8][8];
#pragma unroll
    for (int i = 0; i < 8; i++)
#pragma unroll
        for (int u = 0; u < 8; u++) acc[i][u] = 0.0f;

    for (int kt = 0; kt < DMODEL; kt += BK) {
#pragma unroll
        for (int l = 0; l < 2; l++) {
            int idx = tid + l * 256;          // 0..511
            int row = idx >> 2;               // 0..127
            int kq = (idx & 3) << 2;          // 0,4,8,12
            float4 va = *(const float4*)(X + (size_t)(m0 + row) * DMODEL + kt + kq);
            As[kq + 0][row] = va.x; As[kq + 1][row] = va.y;
            As[kq + 2][row] = va.z; As[kq + 3][row] = va.w;
            float4 vb = *(const float4*)(W + (size_t)(n0 + row) * DMODEL + kt + kq);
            Bs[kq + 0][row] = vb.x; Bs[kq + 1][row] = vb.y;
            Bs[kq + 2][row] = vb.z; Bs[kq + 3][row] = vb.w;
        }
        __syncthreads();

#pragma unroll
        for (int k = 0; k < BK; k++) {
            float a[8], b[8];
            float4 a0 = *(const float4*)&As[k][tr * 8];
            float4 a1 = *(const float4*)&As[k][tr * 8 + 4];
            a[0] = a0.x; a[1] = a0.y; a[2] = a0.z; a[3] = a0.w;
            a[4] = a1.x; a[5] = a1.y; a[6] = a1.z; a[7] = a1.w;
#pragma unroll
            for (int u = 0; u < 8; u++) b[u] = Bs[k][tc + 16 * u];
#pragma unroll
            for (int i = 0; i < 8; i++)
#pragma unroll
                for (int u = 0; u < 8; u++) acc[i][u] = fmaf(a[i], b[u], acc[i][u]);
        }
        __syncthreads();
    }

#pragma unroll
    for (int i = 0; i < 8; i++) {
        int m = m0 + tr * 8 + i;
#pragma unroll
        for (int u = 0; u < 8; u++) {
            int n = n0 + tc + 16 * u;
            float y = acc[i][u] + bias[n];
            if (scatter) {
                Y[((size_t)(n >> 6) * S_LEN + m) * DK + (n & 63)] = y;
            } else {
                Y[(size_t)m * DMODEL + n] = y;
            }
        }
    }
}

__global__ void __launch_bounds__(256)
qkv_gemm_kernel(const float* __restrict__ q_in, const float* __restrict__ k_in,
                const float* __restrict__ v_in,
                const float* __restrict__ Wq, const float* __restrict__ Wk,
                const float* __restrict__ Wv,
                const float* __restrict__ bq, const float* __restrict__ bk,
                const float* __restrict__ bv)
{
    const float* Xs[3] = {q_in, k_in, v_in};
    const float* Ws[3] = {Wq, Wk, Wv};
    const float* bs[3] = {bq, bk, bv};
    float* dsts[3] = {g_Q, g_K, g_V};
    int z = blockIdx.z;
    gemm_body(Xs[z], Ws[z], bs[z], dsts[z], true);
}

__global__ void __launch_bounds__(256)
out_gemm_kernel(const float* __restrict__ Wo, const float* __restrict__ bo,
                float* __restrict__ out)
{
    gemm_body(g_attn, Wo, bo, out, false);
}

// ---------------------------------------------------------------------------
// Flash attention: one block = (64 query rows, 1 head). 256 threads as a
// 16x16 grid of 4x4 micro-tiles. K stored transposed in SMEM for
// conflict-free float4 column reads; P staged through SMEM for the PV GEMM.
// ---------------------------------------------------------------------------
#define PAD 68          // row stride (floats) for all attention SMEM tiles
#define ATTN_SMEM (4 * 64 * PAD * (int)sizeof(float))   // 69632 B

__global__ void __launch_bounds__(256)
attn_kernel()
{
    extern __shared__ float smem[];
    float* Qs  = smem;               // [64][PAD]  Q rows (pre-scaled)
    float* KsT = Qs  + 64 * PAD;     // [64][PAD]  indexed [d][c] (transposed)
    float* Vs  = KsT + 64 * PAD;     // [64][PAD]  [j][d]
    float* Ps  = Vs  + 64 * PAD;     // [64][PAD]  [r][c]

    const int h  = blockIdx.y;
    const int q0 = blockIdx.x * 64;
    const int tid = threadIdx.x;
    const int tr = tid >> 4;         // row group: rows r0..r0+3
    const int tc = tid & 15;         // col group: cols/dims c0..c0+3
    const int r0 = tr * 4;
    const int c0 = tc * 4;
    const float scale = 0.125f;      // 1/sqrt(64)

    // load Q tile, scaled
    const float* Qg = g_Q + ((size_t)h * S_LEN + q0) * DK;
#pragma unroll
    for (int l = 0; l < 4; l++) {
        int idx = tid + l * 256;     // 0..1023
        int r = idx >> 4;            // 0..63
        int dq = (idx & 15) << 2;    // 0..60
        float4 v = *(const float4*)(Qg + r * DK + dq);
        float4 sv = make_float4(v.x * scale, v.y * scale, v.z * scale, v.w * scale);
        *(float4*)&Qs[r * PAD + dq] = sv;
    }

    float acc[4][4];
    float mrow[4], lrow[4];
#pragma unroll
    for (int i = 0; i < 4; i++) {
        mrow[i] = -1e30f; lrow[i] = 0.0f;
#pragma unroll
        for (int j = 0; j < 4; j++) acc[i][j] = 0.0f;
    }

    for (int t = 0; t < S_LEN; t += 64) {
        const float* Kg = g_K + ((size_t)h * S_LEN + t) * DK;
        const float* Vg = g_V + ((size_t)h * S_LEN + t) * DK;

        __syncthreads();   // previous iteration done reading Ps/Vs/KsT
#pragma unroll
        for (int l = 0; l < 4; l++) {
            int idx = tid + l * 256;
            int c = idx >> 4;
            int dq = (idx & 15) << 2;
            float4 kv = *(const float4*)(Kg + c * DK + dq);
            KsT[(dq + 0) * PAD + c] = kv.x;
            KsT[(dq + 1) * PAD + c] = kv.y;
            KsT[(dq + 2) * PAD + c] = kv.z;
            KsT[(dq + 3) * PAD + c] = kv.w;
            float4 vv = *(const float4*)(Vg + c * DK + dq);
            *(float4*)&Vs[c * PAD + dq] = vv;
        }
        __syncthreads();

        // S = Q K^T (scaled): s[i][j] = sum_d Qs[r0+i][d] * KsT[d][c0+j]
        float s[4][4];
#pragma unroll
        for (int i = 0; i < 4; i++)
#pragma unroll
            for (int j = 0; j < 4; j++) s[i][j] = 0.0f;

#pragma unroll
        for (int d = 0; d < DK; d += 4) {
            float4 kk0 = *(const float4*)&KsT[(d + 0) * PAD + c0];
            float4 kk1 = *(const float4*)&KsT[(d + 1) * PAD + c0];
            float4 kk2 = *(const float4*)&KsT[(d + 2) * PAD + c0];
            float4 kk3 = *(const float4*)&KsT[(d + 3) * PAD + c0];
#pragma unroll
            for (int i = 0; i < 4; i++) {
                float4 qq = *(const float4*)&Qs[(r0 + i) * PAD + d];
                s[i][0] = fmaf(qq.x, kk0.x, fmaf(qq.y, kk1.x, fmaf(qq.z, kk2.x, fmaf(qq.w, kk3.x, s[i][0]))));
                s[i][1] = fmaf(qq.x, kk0.y, fmaf(qq.y, kk1.y, fmaf(qq.z, kk2.y, fmaf(qq.w, kk3.y, s[i][1]))));
                s[i][2] = fmaf(qq.x, kk0.z, fmaf(qq.y, kk1.z, fmaf(qq.z, kk2.z, fmaf(qq.w, kk3.z, s[i][2]))));
                s[i][3] = fmaf(qq.x, kk0.w, fmaf(qq.y, kk1.w, fmaf(qq.z, kk2.w, fmaf(qq.w, kk3.w, s[i][3]))));
            }
        }

        // online softmax per row (16 threads per row share via shfl over 16 lanes)
#pragma unroll
        for (int i = 0; i < 4; i++) {
            float mx = fmaxf(fmaxf(s[i][0], s[i][1]), fmaxf(s[i][2], s[i][3]));
#pragma unroll
            for (int o = 8; o >= 1; o >>= 1)
                mx = fmaxf(mx, __shfl_xor_sync(0xffffffffu, mx, o));
            float mnew = fmaxf(mrow[i], mx);
            float alpha = __expf(mrow[i] - mnew);
            float sum = 0.0f;
#pragma unroll
            for (int j = 0; j < 4; j++) {
                float p = __expf(s[i][j] - mnew);
                s[i][j] = p;
                sum += p;
            }
#pragma unroll
            for (int o = 8; o >= 1; o >>= 1)
                sum += __shfl_xor_sync(0xffffffffu, sum, o);
            lrow[i] = lrow[i] * alpha + sum;
            mrow[i] = mnew;
#pragma unroll
            for (int j = 0; j < 4; j++) acc[i][j] *= alpha;
            *(float4*)&Ps[(r0 + i) * PAD + c0] =
                make_float4(s[i][0], s[i][1], s[i][2], s[i][3]);
        }
        __syncthreads();

        // O += P V: acc[i][j] += sum_k Ps[r0+i][k] * Vs[k][c0+j]
#pragma unroll
        for (int kk = 0; kk < 64; kk += 4) {
            float4 vv0 = *(const float4*)&Vs[(kk + 0) * PAD + c0];
            float4 vv1 = *(const float4*)&Vs[(kk + 1) * PAD + c0];
            float4 vv2 = *(const float4*)&Vs[(kk + 2) * PAD + c0];
            float4 vv3 = *(const float4*)&Vs[(kk + 3) * PAD + c0];
#pragma unroll
            for (int i = 0; i < 4; i++) {
                float4 pp = *(const float4*)&Ps[(r0 + i) * PAD + kk];
                acc[i][0] = fmaf(pp.x, vv0.x, fmaf(pp.y, vv1.x, fmaf(pp.z, vv2.x, fmaf(pp.w, vv3.x, acc[i][0]))));
                acc[i][1] = fmaf(pp.x, vv0.y, fmaf(pp.y, vv1.y, fmaf(pp.z, vv2.y, fmaf(pp.w, vv3.y, acc[i][1]))));
                acc[i][2] = fmaf(pp.x, vv0.z, fmaf(pp.y, vv1.z, fmaf(pp.z, vv2.z, fmaf(pp.w, vv3.z, acc[i][2]))));
                acc[i][3] = fmaf(pp.x, vv0.w, fmaf(pp.y, vv1.w, fmaf(pp.z, vv2.w, fmaf(pp.w, vv3.w, acc[i][3]))));
            }
        }
    }

    // epilogue: normalize and write [S, DMODEL] row-major at head offset
#pragma unroll
    for (int i = 0; i < 4; i++) {
        float inv = 1.0f / lrow[i];
        int r = q0 + r0 + i;
        float4 o = make_float4(acc[i][0] * inv, acc[i][1] * inv,
                               acc[i][2] * inv, acc[i][3] * inv);
        *(float4*)&g_attn[(size_t)r * DMODEL + h * DK + c0] = o;
    }
}

// ---------------------------------------------------------------------------
extern "C" void kernel_launch(void* const* d_in, const int* in_sizes, int n_in,
                              void* d_out, int out_size)
{
    (void)in_sizes; (void)n_in; (void)out_size;
    const float* q  = (const float*)d_in[0];
    const float* k  = (const float*)d_in[1];
    const float* v  = (const float*)d_in[2];
    const float* Wq = (const float*)d_in[3];
    const float* bq = (const float*)d_in[4];
    const float* Wk = (const float*)d_in[5];
    const float* bk = (const float*)d_in[6];
    const float* Wv = (const float*)d_in[7];
    const float* bv = (const float*)d_in[8];
    const float* Wo = (const float*)d_in[9];
    const float* bo = (const float*)d_in[10];
    float* out = (float*)d_out;

    cudaFuncSetAttribute(attn_kernel,
                         cudaFuncAttributeMaxDynamicSharedMemorySize, ATTN_SMEM);

    // 1) Q/K/V projections (batched over z)
    dim3 gqkv(DMODEL / BN, S_LEN / BM, 3);
    qkv_gemm_kernel<<<gqkv, 256>>>(q, k, v, Wq, Wk, Wv, bq, bk, bv);

    // 2) attention
    dim3 gattn(S_LEN / 64, NHEAD);
    attn_kernel<<<gattn, 256, ATTN_SMEM>>>();

    // 3) output projection
    dim3 gout(DMODEL / BN, S_LEN / BM);
    out_gemm_kernel<<<gout, 256>>>(Wo, bo, out);
}

// round 2
// speedup vs baseline: 1.0521x; 1.0521x over previous
#include <cuda_runtime.h>
#include <math.h>

// ---------------------------------------------------------------------------
// MultiHeadAttention: B=1, S=4096, D_MODEL=1024, H=16, d_k=64, fp32.
//   Q = q @ Wq^T + bq ; K,V likewise   (stored head-major [H][S][64])
//   attn = softmax(Q K^T / 8) V        (flash-attention tiles 64x64)
//   out  = attn @ Wo^T + bo
// ---------------------------------------------------------------------------

#define S_LEN 4096
#define DMODEL 1024
#define NHEAD 16
#define DK 64

#define BM 128
#define BN 128
#define BK 16

// scratch (allocation-free rule: __device__ globals)
__device__ float g_Q[NHEAD * S_LEN * DK];
__device__ float g_K[NHEAD * S_LEN * DK];
__device__ float g_V[NHEAD * S_LEN * DK];
__device__ float g_attn[S_LEN * DMODEL];

// ---------------------------------------------------------------------------
// GEMM body: Y[m,n] = sum_k X[m,k] * W[n,k] + bias[n]
// M=4096, N=1024, K=1024. Block tile 128x128, K-tile 16, 256 threads,
// 8x8 per thread (columns strided by 16 for conflict-free SMEM reads).
// scatter: write into head-major layout dst[((n>>6)*S + m)*64 + (n&63)].
// ---------------------------------------------------------------------------
__device__ __forceinline__ void gemm_body(
    const float* __restrict__ X, const float* __restrict__ W,
    const float* __restrict__ bias, float* __restrict__ Y, bool scatter)
{
    __shared__ float As[BK][BM + 4];
    __shared__ float Bs[BK][BN + 4];

    const int tid = threadIdx.x;
    const int tr = tid >> 4;      // 0..15 -> output rows tr*8..tr*8+7
    const int tc = tid & 15;      // 0..15 -> output cols tc + 16*u
    const int m0 = blockIdx.y * BM;
    const int n0 = blockIdx.x * BN;

    float acc[8][8];
#pragma unroll
    for (int i = 0; i < 8; i++)
#pragma unroll
        for (int u = 0; u < 8; u++) acc[i][u] = 0.0f;

    for (int kt = 0; kt < DMODEL; kt += BK) {
#pragma unroll
        for (int l = 0; l < 2; l++) {
            int idx = tid + l * 256;          // 0..511
            int row = idx >> 2;               // 0..127
            int kq = (idx & 3) << 2;          // 0,4,8,12
            float4 va = *(const float4*)(X + (size_t)(m0 + row) * DMODEL + kt + kq);
            As[kq + 0][row] = va.x; As[kq + 1][row] = va.y;
            As[kq + 2][row] = va.z; As[kq + 3][row] = va.w;
            float4 vb = *(const float4*)(W + (size_t)(n0 + row) * DMODEL + kt + kq);
            Bs[kq + 0][row] = vb.x; Bs[kq + 1][row] = vb.y;
            Bs[kq + 2][row] = vb.z; Bs[kq + 3][row] = vb.w;
        }
        __syncthreads();

#pragma unroll
        for (int k = 0; k < BK; k++) {
            float a[8], b[8];
            float4 a0 = *(const float4*)&As[k][tr * 8];
            float4 a1 = *(const float4*)&As[k][tr * 8 + 4];
            a[0] = a0.x; a[1] = a0.y; a[2] = a0.z; a[3] = a0.w;
            a[4] = a1.x; a[5] = a1.y; a[6] = a1.z; a[7] = a1.w;
#pragma unroll
            for (int u = 0; u < 8; u++) b[u] = Bs[k][tc + 16 * u];
#pragma unroll
            for (int i = 0; i < 8; i++)
#pragma unroll
                for (int u = 0; u < 8; u++) acc[i][u] = fmaf(a[i], b[u], acc[i][u]);
        }
        __syncthreads();
    }

#pragma unroll
    for (int i = 0; i < 8; i++) {
        int m = m0 + tr * 8 + i;
#pragma unroll
        for (int u = 0; u < 8; u++) {
            int n = n0 + tc + 16 * u;
            float y = acc[i][u] + bias[n];
            if (scatter) {
                Y[((size_t)(n >> 6) * S_LEN + m) * DK + (n & 63)] = y;
            } else {
                Y[(size_t)m * DMODEL + n] = y;
            }
        }
    }
}

__global__ void __launch_bounds__(256)
qkv_gemm_kernel(const float* __restrict__ q_in, const float* __restrict__ k_in,
                const float* __restrict__ v_in,
                const float* __restrict__ Wq, const float* __restrict__ Wk,
                const float* __restrict__ Wv,
                const float* __restrict__ bq, const float* __restrict__ bk,
                const float* __restrict__ bv)
{
    const float* Xs[3] = {q_in, k_in, v_in};
    const float* Ws[3] = {Wq, Wk, Wv};
    const float* bs[3] = {bq, bk, bv};
    float* dsts[3] = {g_Q, g_K, g_V};
    int z = blockIdx.z;
    gemm_body(Xs[z], Ws[z], bs[z], dsts[z], true);
}

__global__ void __launch_bounds__(256)
out_gemm_kernel(const float* __restrict__ Wo, const float* __restrict__ bo,
                float* __restrict__ out)
{
    gemm_body(g_attn, Wo, bo, out, false);
}

// ---------------------------------------------------------------------------
// Flash attention: one block = (64 query rows, 1 head). 256 threads as a
// 16x16 grid of 4x4 micro-tiles. K stored transposed in SMEM for
// conflict-free float4 column reads; P staged through SMEM for the PV GEMM.
// ---------------------------------------------------------------------------
#define PAD 68          // row stride (floats) for all attention SMEM tiles
#define ATTN_SMEM (4 * 64 * PAD * (int)sizeof(float))   // 69632 B

__global__ void __launch_bounds__(256)
attn_kernel()
{
    extern __shared__ float smem[];
    float* Qs  = smem;               // [64][PAD]  Q rows (pre-scaled)
    float* KsT = Qs  + 64 * PAD;     // [64][PAD]  indexed [d][c] (transposed)
    float* Vs  = KsT + 64 * PAD;     // [64][PAD]  [j][d]
    float* Ps  = Vs  + 64 * PAD;     // [64][PAD]  [r][c]

    const int h  = blockIdx.y;
    const int q0 = blockIdx.x * 64;
    const int tid = threadIdx.x;
    const int tr = tid >> 4;         // row group: rows r0..r0+3
    const int tc = tid & 15;         // col group: cols/dims c0..c0+3
    const int r0 = tr * 4;
    const int c0 = tc * 4;
    const float scale = 0.125f;      // 1/sqrt(64)

    // load Q tile, scaled
    const float* Qg = g_Q + ((size_t)h * S_LEN + q0) * DK;
#pragma unroll
    for (int l = 0; l < 4; l++) {
        int idx = tid + l * 256;     // 0..1023
        int r = idx >> 4;            // 0..63
        int dq = (idx & 15) << 2;    // 0..60
        float4 v = *(const float4*)(Qg + r * DK + dq);
        float4 sv = make_float4(v.x * scale, v.y * scale, v.z * scale, v.w * scale);
        *(float4*)&Qs[r * PAD + dq] = sv;
    }

    float acc[4][4];
    float mrow[4], lrow[4];
#pragma unroll
    for (int i = 0; i < 4; i++) {
        mrow[i] = -1e30f; lrow[i] = 0.0f;
#pragma unroll
        for (int j = 0; j < 4; j++) acc[i][j] = 0.0f;
    }

    for (int t = 0; t < S_LEN; t += 64) {
        const float* Kg = g_K + ((size_t)h * S_LEN + t) * DK;
        const float* Vg = g_V + ((size_t)h * S_LEN + t) * DK;

        __syncthreads();   // previous iteration done reading Ps/Vs/KsT
#pragma unroll
        for (int l = 0; l < 4; l++) {
            int idx = tid + l * 256;
            int c = idx >> 4;
            int dq = (idx & 15) << 2;
            float4 kv = *(const float4*)(Kg + c * DK + dq);
            KsT[(dq + 0) * PAD + c] = kv.x;
            KsT[(dq + 1) * PAD + c] = kv.y;
            KsT[(dq + 2) * PAD + c] = kv.z;
            KsT[(dq + 3) * PAD + c] = kv.w;
            float4 vv = *(const float4*)(Vg + c * DK + dq);
            *(float4*)&Vs[c * PAD + dq] = vv;
        }
        __syncthreads();

        // S = Q K^T (scaled): s[i][j] = sum_d Qs[r0+i][d] * KsT[d][c0+j]
        float s[4][4];
#pragma unroll
        for (int i = 0; i < 4; i++)
#pragma unroll
            for (int j = 0; j < 4; j++) s[i][j] = 0.0f;

#pragma unroll
        for (int d = 0; d < DK; d += 4) {
            float4 kk0 = *(const float4*)&KsT[(d + 0) * PAD + c0];
            float4 kk1 = *(const float4*)&KsT[(d + 1) * PAD + c0];
            float4 kk2 = *(const float4*)&KsT[(d + 2) * PAD + c0];
            float4 kk3 = *(const float4*)&KsT[(d + 3) * PAD + c0];
#pragma unroll
            for (int i = 0; i < 4; i++) {
                float4 qq = *(const float4*)&Qs[(r0 + i) * PAD + d];
                s[i][0] = fmaf(qq.x, kk0.x, fmaf(qq.y, kk1.x, fmaf(qq.z, kk2.x, fmaf(qq.w, kk3.x, s[i][0]))));
                s[i][1] = fmaf(qq.x, kk0.y, fmaf(qq.y, kk1.y, fmaf(qq.z, kk2.y, fmaf(qq.w, kk3.y, s[i][1]))));
                s[i][2] = fmaf(qq.x, kk0.z, fmaf(qq.y, kk1.z, fmaf(qq.z, kk2.z, fmaf(qq.w, kk3.z, s[i][2]))));
                s[i][3] = fmaf(qq.x, kk0.w, fmaf(qq.y, kk1.w, fmaf(qq.z, kk2.w, fmaf(qq.w, kk3.w, s[i][3]))));
            }
        }

        // online softmax per row (16 threads per row share via shfl over 16 lanes)
#pragma unroll
        for (int i = 0; i < 4; i++) {
            float mx = fmaxf(fmaxf(s[i][0], s[i][1]), fmaxf(s[i][2], s[i][3]));
#pragma unroll
            for (int o = 8; o >= 1; o >>= 1)
                mx = fmaxf(mx, __shfl_xor_sync(0xffffffffu, mx, o));
            float mnew = fmaxf(mrow[i], mx);
            float alpha = __expf(mrow[i] - mnew);
            float sum = 0.0f;
#pragma unroll
            for (int j = 0; j < 4; j++) {
                float p = __expf(s[i][j] - mnew);
                s[i][j] = p;
                sum += p;
            }
#pragma unroll
            for (int o = 8; o >= 1; o >>= 1)
                sum += __shfl_xor_sync(0xffffffffu, sum, o);
            lrow[i] = lrow[i] * alpha + sum;
            mrow[i] = mnew;
#pragma unroll
            for (int j = 0; j < 4; j++) acc[i][j] *= alpha;
            *(float4*)&Ps[(r0 + i) * PAD + c0] =
                make_float4(s[i][0], s[i][1], s[i][2], s[i][3]);
        }
        __syncthreads();

        // O += P V: acc[i][j] += sum_k Ps[r0+i][k] * Vs[k][c0+j]
#pragma unroll
        for (int kk = 0; kk < 64; kk += 4) {
            float4 vv0 = *(const float4*)&Vs[(kk + 0) * PAD + c0];
            float4 vv1 = *(const float4*)&Vs[(kk + 1) * PAD + c0];
            float4 vv2 = *(const float4*)&Vs[(kk + 2) * PAD + c0];
            float4 vv3 = *(const float4*)&Vs[(kk + 3) * PAD + c0];
#pragma unroll
            for (int i = 0; i < 4; i++) {
                float4 pp = *(const float4*)&Ps[(r0 + i) * PAD + kk];
                acc[i][0] = fmaf(pp.x, vv0.x, fmaf(pp.y, vv1.x, fmaf(pp.z, vv2.x, fmaf(pp.w, vv3.x, acc[i][0]))));
                acc[i][1] = fmaf(pp.x, vv0.y, fmaf(pp.y, vv1.y, fmaf(pp.z, vv2.y, fmaf(pp.w, vv3.y, acc[i][1]))));
                acc[i][2] = fmaf(pp.x, vv0.z, fmaf(pp.y, vv1.z, fmaf(pp.z, vv2.z, fmaf(pp.w, vv3.z, acc[i][2]))));
                acc[i][3] = fmaf(pp.x, vv0.w, fmaf(pp.y, vv1.w, fmaf(pp.z, vv2.w, fmaf(pp.w, vv3.w, acc[i][3]))));
            }
        }
    }

    // epilogue: normalize and write [S, DMODEL] row-major at head offset
#pragma unroll
    for (int i = 0; i < 4; i++) {
        float inv = 1.0f / lrow[i];
        int r = q0 + r0 + i;
        float4 o = make_float4(acc[i][0] * inv, acc[i][1] * inv,
                               acc[i][2] * inv, acc[i][3] * inv);
        *(float4*)&g_attn[(size_t)r * DMODEL + h * DK + c0] = o;
    }
}

// ---------------------------------------------------------------------------
extern "C" void kernel_launch(void* const* d_in, const int* in_sizes, int n_in,
                              void* d_out, int out_size)
{
    (void)in_sizes; (void)n_in; (void)out_size;
    const float* q  = (const float*)d_in[0];
    const float* k  = (const float*)d_in[1];
    const float* v  = (const float*)d_in[2];
    const float* Wq = (const float*)d_in[3];
    const float* bq = (const float*)d_in[4];
    const float* Wk = (const float*)d_in[5];
    const float* bk = (const float*)d_in[6];
    const float* Wv = (const float*)d_in[7];
    const float* bv = (const float*)d_in[8];
    const float* Wo = (const float*)d_in[9];
    const float* bo = (const float*)d_in[10];
    float* out = (float*)d_out;

    cudaFuncSetAttribute(attn_kernel,
                         cudaFuncAttributeMaxDynamicSharedMemorySize, ATTN_SMEM);

    // 1) Q/K/V projections (batched over z)
    dim3 gqkv(DMODEL / BN, S_LEN / BM, 3);
    qkv_gemm_kernel<<<gqkv, 256>>>(q, k, v, Wq, Wk, Wv, bq, bk, bv);

    // 2) attention
    dim3 gattn(S_LEN / 64, NHEAD);
    attn_kernel<<<gattn, 256, ATTN_SMEM>>>();

    // 3) output projection
    dim3 gout(DMODEL / BN, S_LEN / BM);
    out_gemm_kernel<<<gout, 256>>>(Wo, bo, out);
}

// round 4
// speedup vs baseline: 2.2492x; 2.1379x over previous
#include <cuda_runtime.h>
#include <cuda_bf16.h>
#include <math.h>
#include <stdint.h>

// ---------------------------------------------------------------------------
// MultiHeadAttention: B=1, S=4096, D_MODEL=1024, H=16, d_k=64, fp32.
// All GEMMs (projections + attention) on tensor cores via baseline-PTX
// mma.sync m16n8k16 bf16 with hi/lo (bf16x3) error compensation.
// ---------------------------------------------------------------------------

#define S_LEN 4096
#define DMODEL 1024
#define NHEAD 16
#define DK 64

// scratch (allocation-free rule: __device__ globals)
__device__ float g_Q[NHEAD * S_LEN * DK];
__device__ float g_K[NHEAD * S_LEN * DK];
__device__ float g_V[NHEAD * S_LEN * DK];
__device__ float g_attn[S_LEN * DMODEL];

// ============================ mma helpers ==================================
__device__ __forceinline__ void mma_bf16(float c[4], const uint32_t a[4],
                                         const uint32_t b[2]) {
    asm volatile(
        "mma.sync.aligned.m16n8k16.row.col.f32.bf16.bf16.f32 "
        "{%0,%1,%2,%3}, {%4,%5,%6,%7}, {%8,%9}, {%0,%1,%2,%3};"
        : "+f"(c[0]), "+f"(c[1]), "+f"(c[2]), "+f"(c[3])
        : "r"(a[0]), "r"(a[1]), "r"(a[2]), "r"(a[3]), "r"(b[0]), "r"(b[1]));
}

// pack {hi_val -> upper 16, lo_val -> lower 16} as bf16x2
__device__ __forceinline__ uint32_t pack_bf16(float hi, float lo) {
    uint32_t r;
    asm("cvt.rn.bf16x2.f32 %0, %1, %2;" : "=r"(r) : "f"(hi), "f"(lo));
    return r;
}
__device__ __forceinline__ float lo_f(uint32_t p) { return __uint_as_float(p << 16); }
__device__ __forceinline__ float hi_f(uint32_t p) { return __uint_as_float(p & 0xffff0000u); }

// split float4 into bf16 hi pair + bf16 residual pair
__device__ __forceinline__ void split4(float4 v, uint2& h, uint2& l) {
    h.x = pack_bf16(v.y, v.x);
    h.y = pack_bf16(v.w, v.z);
    l.x = pack_bf16(v.y - hi_f(h.x), v.x - lo_f(h.x));
    l.y = pack_bf16(v.w - hi_f(h.y), v.z - lo_f(h.y));
}

// ============================ tensor GEMM ==================================
// Y[m,n] = sum_k X[m,k] * W[n,k] + bias[n],  M=4096, N=1024, K=1024.
// CTA 128x128, 8 warps each 64x32, K chunks of 64, bf16x3.
#define GSTR 72                              // smem row stride (bf16)
#define GEMM_SMEM (4 * 128 * GSTR * 2)       // Ahi|Alo|Bhi|Blo = 73728 B

__device__ __forceinline__ void tensor_gemm(
    const float* __restrict__ X, const float* __restrict__ W,
    const float* __restrict__ bias, float* __restrict__ Y, int scatter)
{
    extern __shared__ __align__(16) uint16_t sm[];
    uint16_t* Ahi = sm;                       // [128][72]
    uint16_t* Alo = sm + 128 * GSTR;
    uint16_t* Bhi = sm + 2 * 128 * GSTR;
    uint16_t* Blo = sm + 3 * 128 * GSTR;

    const int tid = threadIdx.x;
    const int lane = tid & 31;
    const int w = tid >> 5;
    const int wm = (w >> 2) * 64;
    const int wn = (w & 3) * 32;
    const int m0 = blockIdx.y * 128;
    const int n0 = blockIdx.x * 128;
    const int r4 = lane >> 2;        // 0..7
    const int s2 = (lane & 3) * 2;   // 0,2,4,6

    float c[4][4][4];
#pragma unroll
    for (int mt = 0; mt < 4; mt++)
#pragma unroll
        for (int nt = 0; nt < 4; nt++)
#pragma unroll
            for (int i = 0; i < 4; i++) c[mt][nt][i] = 0.0f;

    for (int ch = 0; ch < 16; ch++) {
        const int kt = ch * 64;
        // prefetch gmem into regs (hides under previous chunk's mma)
        float4 ra[8], rb[8];
#pragma unroll
        for (int i = 0; i < 8; i++) {
            int q = i * 256 + tid;
            int row = q >> 4, c4 = q & 15;
            ra[i] = *(const float4*)(X + (size_t)(m0 + row) * DMODEL + kt + c4 * 4);
            rb[i] = *(const float4*)(W + (size_t)(n0 + row) * DMODEL + kt + c4 * 4);
        }
        __syncthreads();   // previous chunk's mma done reading smem
#pragma unroll
        for (int i = 0; i < 8; i++) {
            int q = i * 256 + tid;
            int row = q >> 4, c4 = q & 15;
            uint2 h, l;
            split4(ra[i], h, l);
            *(uint2*)&Ahi[row * GSTR + c4 * 4] = h;
            *(uint2*)&Alo[row * GSTR + c4 * 4] = l;
            split4(rb[i], h, l);
            *(uint2*)&Bhi[row * GSTR + c4 * 4] = h;
            *(uint2*)&Blo[row * GSTR + c4 * 4] = l;
        }
        __syncthreads();

#pragma unroll
        for (int kk = 0; kk < 64; kk += 16) {
            uint32_t ah[4][4], al[4][4], bh[4][2], bl[4][2];
#pragma unroll
            for (int mt = 0; mt < 4; mt++) {
                int r = wm + mt * 16 + r4;
                int ci = kk + s2;
                ah[mt][0] = *(const uint32_t*)&Ahi[r * GSTR + ci];
                ah[mt][1] = *(const uint32_t*)&Ahi[(r + 8) * GSTR + ci];
                ah[mt][2] = *(const uint32_t*)&Ahi[r * GSTR + ci + 8];
                ah[mt][3] = *(const uint32_t*)&Ahi[(r + 8) * GSTR + ci + 8];
                al[mt][0] = *(const uint32_t*)&Alo[r * GSTR + ci];
                al[mt][1] = *(const uint32_t*)&Alo[(r + 8) * GSTR + ci];
                al[mt][2] = *(const uint32_t*)&Alo[r * GSTR + ci + 8];
                al[mt][3] = *(const uint32_t*)&Alo[(r + 8) * GSTR + ci + 8];
            }
#pragma unroll
            for (int nt = 0; nt < 4; nt++) {
                int n = wn + nt * 8 + r4;
                int ci = kk + s2;
                bh[nt][0] = *(const uint32_t*)&Bhi[n * GSTR + ci];
                bh[nt][1] = *(const uint32_t*)&Bhi[n * GSTR + ci + 8];
                bl[nt][0] = *(const uint32_t*)&Blo[n * GSTR + ci];
                bl[nt][1] = *(const uint32_t*)&Blo[n * GSTR + ci + 8];
            }
#pragma unroll
            for (int mt = 0; mt < 4; mt++)
#pragma unroll
                for (int nt = 0; nt < 4; nt++) {
                    mma_bf16(c[mt][nt], ah[mt], bh[nt]);
                    mma_bf16(c[mt][nt], ah[mt], bl[nt]);
                    mma_bf16(c[mt][nt], al[mt], bh[nt]);
                }
        }
    }

    // epilogue: bias + store (optionally head-major scatter)
#pragma unroll
    for (int mt = 0; mt < 4; mt++) {
        int row = m0 + wm + mt * 16 + r4;
#pragma unroll
        for (int nt = 0; nt < 4; nt++) {
            int col = n0 + wn + nt * 8 + s2;
            float b0 = bias[col], b1 = bias[col + 1];
            float2 v0 = make_float2(c[mt][nt][0] + b0, c[mt][nt][1] + b1);
            float2 v1 = make_float2(c[mt][nt][2] + b0, c[mt][nt][3] + b1);
            if (scatter) {
                float* d0 = Y + ((size_t)(col >> 6) * S_LEN + row) * DK + (col & 63);
                *(float2*)d0 = v0;
                *(float2*)(d0 + 8 * DK) = v1;
            } else {
                float* d0 = Y + (size_t)row * DMODEL + col;
                *(float2*)d0 = v0;
                *(float2*)(d0 + 8 * DMODEL) = v1;
            }
        }
    }
}

__global__ void __launch_bounds__(256)
qkv_tensor_kernel(const float* __restrict__ q_in, const float* __restrict__ k_in,
                  const float* __restrict__ v_in,
                  const float* __restrict__ Wq, const float* __restrict__ Wk,
                  const float* __restrict__ Wv,
                  const float* __restrict__ bq, const float* __restrict__ bk,
                  const float* __restrict__ bv)
{
    const float* Xs[3] = {q_in, k_in, v_in};
    const float* Ws[3] = {Wq, Wk, Wv};
    const float* bs[3] = {bq, bk, bv};
    float* dsts[3] = {g_Q, g_K, g_V};
    int z = blockIdx.z;
    tensor_gemm(Xs[z], Ws[z], bs[z], dsts[z], 1);
}

__global__ void __launch_bounds__(256)
out_tensor_kernel(const float* __restrict__ Wo, const float* __restrict__ bo,
                  float* __restrict__ out)
{
    tensor_gemm(g_attn, Wo, bo, out, 0);
}

// ============================ attention ====================================
// CTA = 128 q-rows x 1 head, 8 warps x 16 rows. 64-key tiles.
// S = Q K^T via mma (bf16x3), online softmax in accumulator layout,
// P repacked register->A-fragment, PV via mma (bf16x3) with V transposed.
#define VSTR 66
// Qhi/Qlo [128][72], Khi/Klo [64][72], Vhi/Vlo [64][66] (transposed [d][key])
#define OFF_QLO (128 * GSTR)
#define OFF_KHI (2 * 128 * GSTR)
#define OFF_KLO (OFF_KHI + 64 * GSTR)
#define OFF_VHI (OFF_KLO + 64 * GSTR)
#define OFF_VLO (OFF_VHI + 64 * VSTR)
#define ATTN_SMEM ((OFF_VLO + 64 * VSTR) * 2)   // 72192 B

__global__ void __launch_bounds__(256)
attn_mma_kernel()
{
    extern __shared__ __align__(16) uint16_t sm[];
    uint16_t* Qhi = sm;
    uint16_t* Qlo = sm + OFF_QLO;
    uint16_t* Khi = sm + OFF_KHI;
    uint16_t* Klo = sm + OFF_KLO;
    uint16_t* Vhi = sm + OFF_VHI;
    uint16_t* Vlo = sm + OFF_VLO;

    const int h = blockIdx.y;
    const int q0 = blockIdx.x * 128;
    const int tid = threadIdx.x;
    const int lane = tid & 31;
    const int w = tid >> 5;
    const int wrow = w * 16;
    const int r4 = lane >> 2;
    const int s2 = (lane & 3) * 2;

    // load Q tile (scaled by 1/8), split hi/lo
    const float* Qg = g_Q + ((size_t)h * S_LEN + q0) * DK;
#pragma unroll
    for (int i = 0; i < 8; i++) {
        int q = i * 256 + tid;
        int row = q >> 4, c4 = q & 15;
        float4 v = *(const float4*)(Qg + row * DK + c4 * 4);
        v.x *= 0.125f; v.y *= 0.125f; v.z *= 0.125f; v.w *= 0.125f;
        uint2 hh, ll;
        split4(v, hh, ll);
        *(uint2*)&Qhi[row * GSTR + c4 * 4] = hh;
        *(uint2*)&Qlo[row * GSTR + c4 * 4] = ll;
    }

    float accO[8][4];
#pragma unroll
    for (int nt = 0; nt < 8; nt++)
#pragma unroll
        for (int i = 0; i < 4; i++) accO[nt][i] = 0.0f;
    float m0r = -1e30f, m1r = -1e30f, l0r = 0.0f, l1r = 0.0f;

    const int vx = tid & 63;          // d index for V transpose-load
    const int vg = (tid >> 6) * 16;   // key group base

    for (int t = 0; t < S_LEN; t += 64) {
        const float* Kg = g_K + ((size_t)h * S_LEN + t) * DK;
        const float* Vg = g_V + ((size_t)h * S_LEN + t) * DK;

        // prefetch
        float4 rk[4];
#pragma unroll
        for (int i = 0; i < 4; i++) {
            int q = i * 256 + tid;
            int row = q >> 4, c4 = q & 15;
            rk[i] = *(const float4*)(Kg + row * DK + c4 * 4);
        }
        float rv[16];
#pragma unroll
        for (int j = 0; j < 16; j++) rv[j] = Vg[(vg + j) * DK + vx];

        __syncthreads();   // previous tile's mma done reading K/V smem
#pragma unroll
        for (int i = 0; i < 4; i++) {
            int q = i * 256 + tid;
            int row = q >> 4, c4 = q & 15;
            uint2 hh, ll;
            split4(rk[i], hh, ll);
            *(uint2*)&Khi[row * GSTR + c4 * 4] = hh;
            *(uint2*)&Klo[row * GSTR + c4 * 4] = ll;
        }
#pragma unroll
        for (int j = 0; j < 16; j++) {
            uint32_t ph = pack_bf16(0.0f, rv[j]);
            float fh = lo_f(ph);
            uint32_t pl = pack_bf16(0.0f, rv[j] - fh);
            Vhi[vx * VSTR + vg + j] = (uint16_t)(ph & 0xffffu);
            Vlo[vx * VSTR + vg + j] = (uint16_t)(pl & 0xffffu);
        }
        __syncthreads();

        // ---- S = Q K^T (scaled) ----
        float cs[8][4];
#pragma unroll
        for (int nt = 0; nt < 8; nt++)
#pragma unroll
            for (int i = 0; i < 4; i++) cs[nt][i] = 0.0f;

#pragma unroll
        for (int kk = 0; kk < 64; kk += 16) {
            uint32_t ah[4], al[4];
            int r = wrow + r4;
            int ci = kk + s2;
            ah[0] = *(const uint32_t*)&Qhi[r * GSTR + ci];
            ah[1] = *(const uint32_t*)&Qhi[(r + 8) * GSTR + ci];
            ah[2] = *(const uint32_t*)&Qhi[r * GSTR + ci + 8];
            ah[3] = *(const uint32_t*)&Qhi[(r + 8) * GSTR + ci + 8];
            al[0] = *(const uint32_t*)&Qlo[r * GSTR + ci];
            al[1] = *(const uint32_t*)&Qlo[(r + 8) * GSTR + ci];
            al[2] = *(const uint32_t*)&Qlo[r * GSTR + ci + 8];
            al[3] = *(const uint32_t*)&Qlo[(r + 8) * GSTR + ci + 8];
#pragma unroll
            for (int nt = 0; nt < 8; nt++) {
                int n = nt * 8 + r4;
                uint32_t bh[2], bl[2];
                bh[0] = *(const uint32_t*)&Khi[n * GSTR + ci];
                bh[1] = *(const uint32_t*)&Khi[n * GSTR + ci + 8];
                bl[0] = *(const uint32_t*)&Klo[n * GSTR + ci];
                bl[1] = *(const uint32_t*)&Klo[n * GSTR + ci + 8];
                mma_bf16(cs[nt], ah, bh);
                mma_bf16(cs[nt], ah, bl);
                mma_bf16(cs[nt], al, bh);
            }
        }

        // ---- online softmax (rows r4 and r4+8 per thread) ----
        float mx0 = -1e30f, mx1 = -1e30f;
#pragma unroll
        for (int nt = 0; nt < 8; nt++) {
            mx0 = fmaxf(mx0, fmaxf(cs[nt][0], cs[nt][1]));
            mx1 = fmaxf(mx1, fmaxf(cs[nt][2], cs[nt][3]));
        }
        mx0 = fmaxf(mx0, __shfl_xor_sync(0xffffffffu, mx0, 1));
        mx0 = fmaxf(mx0, __shfl_xor_sync(0xffffffffu, mx0, 2));
        mx1 = fmaxf(mx1, __shfl_xor_sync(0xffffffffu, mx1, 1));
        mx1 = fmaxf(mx1, __shfl_xor_sync(0xffffffffu, mx1, 2));
        float mn0 = fmaxf(m0r, mx0), mn1 = fmaxf(m1r, mx1);
        float a0 = __expf(m0r - mn0), a1 = __expf(m1r - mn1);
        float sum0 = 0.0f, sum1 = 0.0f;
#pragma unroll
        for (int nt = 0; nt < 8; nt++) {
            cs[nt][0] = __expf(cs[nt][0] - mn0);
            cs[nt][1] = __expf(cs[nt][1] - mn0);
            cs[nt][2] = __expf(cs[nt][2] - mn1);
            cs[nt][3] = __expf(cs[nt][3] - mn1);
            sum0 += cs[nt][0] + cs[nt][1];
            sum1 += cs[nt][2] + cs[nt][3];
        }
        sum0 += __shfl_xor_sync(0xffffffffu, sum0, 1);
        sum0 += __shfl_xor_sync(0xffffffffu, sum0, 2);
        sum1 += __shfl_xor_sync(0xffffffffu, sum1, 1);
        sum1 += __shfl_xor_sync(0xffffffffu, sum1, 2);
        l0r = l0r * a0 + sum0;
        l1r = l1r * a1 + sum1;
        m0r = mn0; m1r = mn1;
#pragma unroll
        for (int nt = 0; nt < 8; nt++) {
            accO[nt][0] *= a0; accO[nt][1] *= a0;
            accO[nt][2] *= a1; accO[nt][3] *= a1;
        }

        // ---- O += P V (P from registers; V transposed in smem) ----
#pragma unroll
        for (int ktk = 0; ktk < 4; ktk++) {
            uint32_t ph[4], pl[4];
            float p0 = cs[2 * ktk][0], p1 = cs[2 * ktk][1];
            float p2 = cs[2 * ktk][2], p3 = cs[2 * ktk][3];
            float p4 = cs[2 * ktk + 1][0], p5 = cs[2 * ktk + 1][1];
            float p6 = cs[2 * ktk + 1][2], p7 = cs[2 * ktk + 1][3];
            ph[0] = pack_bf16(p1, p0);
            ph[1] = pack_bf16(p3, p2);
            ph[2] = pack_bf16(p5, p4);
            ph[3] = pack_bf16(p7, p6);
            pl[0] = pack_bf16(p1 - hi_f(ph[0]), p0 - lo_f(ph[0]));
            pl[1] = pack_bf16(p3 - hi_f(ph[1]), p2 - lo_f(ph[1]));
            pl[2] = pack_bf16(p5 - hi_f(ph[2]), p4 - lo_f(ph[2]));
            pl[3] = pack_bf16(p7 - hi_f(ph[3]), p6 - lo_f(ph[3]));
#pragma unroll
            for (int nt = 0; nt < 8; nt++) {
                int n = nt * 8 + r4;                 // d index
                int ci = ktk * 16 + s2;              // key index
                uint32_t bh[2], bl[2];
                bh[0] = *(const uint32_t*)&Vhi[n * VSTR + ci];
                bh[1] = *(const uint32_t*)&Vhi[n * VSTR + ci + 8];
                bl[0] = *(const uint32_t*)&Vlo[n * VSTR + ci];
                bl[1] = *(const uint32_t*)&Vlo[n * VSTR + ci + 8];
                mma_bf16(accO[nt], ph, bh);
                mma_bf16(accO[nt], ph, bl);
                mma_bf16(accO[nt], pl, bh);
            }
        }
    }

    // epilogue: normalize, write [S, DMODEL] at head offset
    float inv0 = 1.0f / l0r, inv1 = 1.0f / l1r;
    int row = q0 + wrow + r4;
#pragma unroll
    for (int nt = 0; nt < 8; nt++) {
        float* o0 = g_attn + (size_t)row * DMODEL + h * DK + nt * 8 + s2;
        *(float2*)o0 = make_float2(accO[nt][0] * inv0, accO[nt][1] * inv0);
        *(float2*)(o0 + 8 * DMODEL) = make_float2(accO[nt][2] * inv1, accO[nt][3] * inv1);
    }
}

// ---------------------------------------------------------------------------
extern "C" void kernel_launch(void* const* d_in, const int* in_sizes, int n_in,
                              void* d_out, int out_size)
{
    (void)in_sizes; (void)n_in; (void)out_size;
    const float* q  = (const float*)d_in[0];
    const float* k  = (const float*)d_in[1];
    const float* v  = (const float*)d_in[2];
    const float* Wq = (const float*)d_in[3];
    const float* bq = (const float*)d_in[4];
    const float* Wk = (const float*)d_in[5];
    const float* bk = (const float*)d_in[6];
    const float* Wv = (const float*)d_in[7];
    const float* bv = (const float*)d_in[8];
    const float* Wo = (const float*)d_in[9];
    const float* bo = (const float*)d_in[10];
    float* out = (float*)d_out;

    cudaFuncSetAttribute(qkv_tensor_kernel,
                         cudaFuncAttributeMaxDynamicSharedMemorySize, GEMM_SMEM);
    cudaFuncSetAttribute(out_tensor_kernel,
                         cudaFuncAttributeMaxDynamicSharedMemorySize, GEMM_SMEM);
    cudaFuncSetAttribute(attn_mma_kernel,
                         cudaFuncAttributeMaxDynamicSharedMemorySize, ATTN_SMEM);

    // 1) Q/K/V projections (tensor cores, bf16x3)
    dim3 gqkv(DMODEL / 128, S_LEN / 128, 3);
    qkv_tensor_kernel<<<gqkv, 256, GEMM_SMEM>>>(q, k, v, Wq, Wk, Wv, bq, bk, bv);

    // 2) attention (tensor cores, bf16x3)
    dim3 gattn(S_LEN / 128, NHEAD);
    attn_mma_kernel<<<gattn, 256, ATTN_SMEM>>>();

    // 3) output projection (tensor cores, bf16x3)
    dim3 gout(DMODEL / 128, S_LEN / 128);
    out_tensor_kernel<<<gout, 256, GEMM_SMEM>>>(Wo, bo, out);
}

// round 5
// speedup vs baseline: 2.9177x; 1.2972x over previous
#include <cuda_runtime.h>
#include <cuda_bf16.h>
#include <math.h>
#include <stdint.h>

// ---------------------------------------------------------------------------
// MultiHeadAttention: B=1, S=4096, D_MODEL=1024, H=16, d_k=64, fp32.
// All GEMMs on tensor cores (mma.sync m16n8k16 bf16, bf16x3 compensation).
// R4: double-buffered smem (1 sync/tile), ldmatrix.x4 fragment loads,
//     Q-fragments hoisted out of the attention key loop.
// ---------------------------------------------------------------------------

#define S_LEN 4096
#define DMODEL 1024
#define NHEAD 16
#define DK 64

__device__ float g_Q[NHEAD * S_LEN * DK];
__device__ float g_K[NHEAD * S_LEN * DK];
__device__ float g_V[NHEAD * S_LEN * DK];
__device__ float g_attn[S_LEN * DMODEL];

// ============================ helpers ======================================
__device__ __forceinline__ uint32_t smem_u32(const void* p) {
    uint32_t a;
    asm("{ .reg .u64 t; cvta.to.shared.u64 t, %1; cvt.u32.u64 %0, t; }"
        : "=r"(a) : "l"(p));
    return a;
}

__device__ __forceinline__ void mma_bf16(float c[4], const uint32_t a[4],
                                         const uint32_t b0, const uint32_t b1) {
    asm volatile(
        "mma.sync.aligned.m16n8k16.row.col.f32.bf16.bf16.f32 "
        "{%0,%1,%2,%3}, {%4,%5,%6,%7}, {%8,%9}, {%0,%1,%2,%3};"
        : "+f"(c[0]), "+f"(c[1]), "+f"(c[2]), "+f"(c[3])
        : "r"(a[0]), "r"(a[1]), "r"(a[2]), "r"(a[3]), "r"(b0), "r"(b1));
}

__device__ __forceinline__ void ldsm_x4(uint32_t r[4], uint32_t addr) {
    asm volatile("ldmatrix.sync.aligned.m8n8.x4.shared.b16 {%0,%1,%2,%3}, [%4];"
                 : "=r"(r[0]), "=r"(r[1]), "=r"(r[2]), "=r"(r[3]) : "r"(addr));
}

__device__ __forceinline__ uint32_t pack_bf16(float hi, float lo) {
    uint32_t r;
    asm("cvt.rn.bf16x2.f32 %0, %1, %2;" : "=r"(r) : "f"(hi), "f"(lo));
    return r;
}
__device__ __forceinline__ float lo_f(uint32_t p) { return __uint_as_float(p << 16); }
__device__ __forceinline__ float hi_f(uint32_t p) { return __uint_as_float(p & 0xffff0000u); }

__device__ __forceinline__ void split4(float4 v, uint2& h, uint2& l) {
    h.x = pack_bf16(v.y, v.x);
    h.y = pack_bf16(v.w, v.z);
    l.x = pack_bf16(v.y - hi_f(h.x), v.x - lo_f(h.x));
    l.y = pack_bf16(v.w - hi_f(h.y), v.z - lo_f(h.y));
}

// A-type (16x16) ldmatrix lane byte-offset within a [rows][STR] uint16 array
#define A_LANE_OFF(lane, row_base, STR) \
    ((((row_base) + ((lane) & 15)) * (STR) + (((lane) >> 4) * 8)) * 2)
// B-type x4 (two 8-row n-blocks x 16 k) lane byte-offset
#define B_LANE_OFF(lane, n_base, STR) \
    ((((n_base) + (((lane) >> 4) * 8) + ((lane) & 7)) * (STR) + ((((lane) >> 3) & 1) * 8)) * 2)

// ============================ tensor GEMM ==================================
// Y[m,n] = sum_k X[m,k]*W[n,k] + bias[n].  CTA 128x128, warp 64x32,
// K chunks of 64, double-buffered, bf16x3.
#define GSTR 72
#define GB_AHI 0
#define GB_ALO (128 * GSTR)
#define GB_BHI (2 * 128 * GSTR)
#define GB_BLO (3 * 128 * GSTR)
#define GB_ELEMS (4 * 128 * GSTR)
#define GEMM_SMEM (2 * GB_ELEMS * 2)          // 147456 B

__device__ __forceinline__ void gemm_store_chunk(
    uint16_t* buf, const float4* ra, const float4* rb, int tid)
{
#pragma unroll
    for (int i = 0; i < 8; i++) {
        int q = i * 256 + tid;
        int row = q >> 4, c4 = q & 15;
        uint2 h, l;
        split4(ra[i], h, l);
        *(uint2*)&buf[GB_AHI + row * GSTR + c4 * 4] = h;
        *(uint2*)&buf[GB_ALO + row * GSTR + c4 * 4] = l;
        split4(rb[i], h, l);
        *(uint2*)&buf[GB_BHI + row * GSTR + c4 * 4] = h;
        *(uint2*)&buf[GB_BLO + row * GSTR + c4 * 4] = l;
    }
}

__device__ __forceinline__ void tensor_gemm(
    const float* __restrict__ X, const float* __restrict__ W,
    const float* __restrict__ bias, float* __restrict__ Y, int scatter)
{
    extern __shared__ __align__(16) uint16_t sm[];
    const uint32_t sbase = smem_u32(sm);

    const int tid = threadIdx.x;
    const int lane = tid & 31;
    const int w = tid >> 5;
    const int wm = (w >> 2) * 64;
    const int wn = (w & 3) * 32;
    const int m0 = blockIdx.y * 128;
    const int n0 = blockIdx.x * 128;
    const int r4 = lane >> 2;
    const int s2 = (lane & 3) * 2;

    float c[4][4][4];
#pragma unroll
    for (int mt = 0; mt < 4; mt++)
#pragma unroll
        for (int nt = 0; nt < 4; nt++)
#pragma unroll
            for (int i = 0; i < 4; i++) c[mt][nt][i] = 0.0f;

    float4 ra[8], rb[8];
    // preload chunk 0
#pragma unroll
    for (int i = 0; i < 8; i++) {
        int q = i * 256 + tid;
        int row = q >> 4, c4 = q & 15;
        ra[i] = *(const float4*)(X + (size_t)(m0 + row) * DMODEL + c4 * 4);
        rb[i] = *(const float4*)(W + (size_t)(n0 + row) * DMODEL + c4 * 4);
    }
    gemm_store_chunk(sm, ra, rb, tid);
    __syncthreads();

    for (int ch = 0; ch < 16; ch++) {
        const int buf = ch & 1;
        const uint32_t bb = sbase + buf * GB_ELEMS * 2;

        if (ch < 15) {
            const int kt = (ch + 1) * 64;
#pragma unroll
            for (int i = 0; i < 8; i++) {
                int q = i * 256 + tid;
                int row = q >> 4, c4 = q & 15;
                ra[i] = *(const float4*)(X + (size_t)(m0 + row) * DMODEL + kt + c4 * 4);
                rb[i] = *(const float4*)(W + (size_t)(n0 + row) * DMODEL + kt + c4 * 4);
            }
        }

        // ---- MMA on current buffer ----
#pragma unroll
        for (int kk = 0; kk < 64; kk += 16) {
            uint32_t ah[4][4], al[4][4], bh[2][4], bl[2][4];
#pragma unroll
            for (int mt = 0; mt < 4; mt++) {
                uint32_t ao = A_LANE_OFF(lane, wm + mt * 16, GSTR) + kk * 2;
                ldsm_x4(ah[mt], bb + GB_AHI * 2 + ao);
                ldsm_x4(al[mt], bb + GB_ALO * 2 + ao);
            }
#pragma unroll
            for (int np = 0; np < 2; np++) {
                uint32_t bo = B_LANE_OFF(lane, wn + np * 16, GSTR) + kk * 2;
                ldsm_x4(bh[np], bb + GB_BHI * 2 + bo);
                ldsm_x4(bl[np], bb + GB_BLO * 2 + bo);
            }
#pragma unroll
            for (int mt = 0; mt < 4; mt++)
#pragma unroll
                for (int np = 0; np < 2; np++) {
#pragma unroll
                    for (int half = 0; half < 2; half++) {
                        int nt = np * 2 + half;
                        mma_bf16(c[mt][nt], ah[mt], bh[np][half * 2], bh[np][half * 2 + 1]);
                        mma_bf16(c[mt][nt], ah[mt], bl[np][half * 2], bl[np][half * 2 + 1]);
                        mma_bf16(c[mt][nt], al[mt], bh[np][half * 2], bh[np][half * 2 + 1]);
                    }
                }
        }

        if (ch < 15)
            gemm_store_chunk(sm + (buf ^ 1) * GB_ELEMS, ra, rb, tid);
        __syncthreads();
    }

    // epilogue
#pragma unroll
    for (int mt = 0; mt < 4; mt++) {
        int row = m0 + wm + mt * 16 + r4;
#pragma unroll
        for (int nt = 0; nt < 4; nt++) {
            int col = n0 + wn + nt * 8 + s2;
            float b0 = bias[col], b1 = bias[col + 1];
            float2 v0 = make_float2(c[mt][nt][0] + b0, c[mt][nt][1] + b1);
            float2 v1 = make_float2(c[mt][nt][2] + b0, c[mt][nt][3] + b1);
            if (scatter) {
                float* d0 = Y + ((size_t)(col >> 6) * S_LEN + row) * DK + (col & 63);
                *(float2*)d0 = v0;
                *(float2*)(d0 + 8 * DK) = v1;
            } else {
                float* d0 = Y + (size_t)row * DMODEL + col;
                *(float2*)d0 = v0;
                *(float2*)(d0 + 8 * DMODEL) = v1;
            }
        }
    }
}

__global__ void __launch_bounds__(256)
qkv_tensor_kernel(const float* __restrict__ q_in, const float* __restrict__ k_in,
                  const float* __restrict__ v_in,
                  const float* __restrict__ Wq, const float* __restrict__ Wk,
                  const float* __restrict__ Wv,
                  const float* __restrict__ bq, const float* __restrict__ bk,
                  const float* __restrict__ bv)
{
    const float* Xs[3] = {q_in, k_in, v_in};
    const float* Ws[3] = {Wq, Wk, Wv};
    const float* bs[3] = {bq, bk, bv};
    float* dsts[3] = {g_Q, g_K, g_V};
    int z = blockIdx.z;
    tensor_gemm(Xs[z], Ws[z], bs[z], dsts[z], 1);
}

__global__ void __launch_bounds__(256)
out_tensor_kernel(const float* __restrict__ Wo, const float* __restrict__ bo,
                  float* __restrict__ out)
{
    tensor_gemm(g_attn, Wo, bo, out, 0);
}

// ============================ attention ====================================
// CTA = 128 q-rows x 1 head, 8 warps x 16 rows, 64-key tiles, double-buffered.
#define VSTR 72
// smem (uint16 elems): Qhi|Qlo then 2 KV buffers {Khi,Klo,Vhi,Vlo}
#define AQ_HI 0
#define AQ_LO (128 * GSTR)
#define AKV_BASE (2 * 128 * GSTR)
#define AB_KHI 0
#define AB_KLO (64 * GSTR)
#define AB_VHI (2 * 64 * GSTR)
#define AB_VLO (2 * 64 * GSTR + 64 * VSTR)
#define AKV_ELEMS (2 * 64 * GSTR + 2 * 64 * VSTR)
#define ATTN_SMEM ((AKV_BASE + 2 * AKV_ELEMS) * 2)    // 110592 B

__device__ __forceinline__ void attn_store_tile(
    uint16_t* buf, const float4* rk, const float* rv, int tid, int vx, int vg)
{
#pragma unroll
    for (int i = 0; i < 4; i++) {
        int q = i * 256 + tid;
        int row = q >> 4, c4 = q & 15;
        uint2 hh, ll;
        split4(rk[i], hh, ll);
        *(uint2*)&buf[AB_KHI + row * GSTR + c4 * 4] = hh;
        *(uint2*)&buf[AB_KLO + row * GSTR + c4 * 4] = ll;
    }
#pragma unroll
    for (int j = 0; j < 16; j++) {
        uint32_t ph = pack_bf16(0.0f, rv[j]);
        float fh = lo_f(ph);
        uint32_t pl = pack_bf16(0.0f, rv[j] - fh);
        buf[AB_VHI + vx * VSTR + vg + j] = (uint16_t)(ph & 0xffffu);
        buf[AB_VLO + vx * VSTR + vg + j] = (uint16_t)(pl & 0xffffu);
    }
}

__global__ void __launch_bounds__(256)
attn_mma_kernel()
{
    extern __shared__ __align__(16) uint16_t sm[];
    const uint32_t sbase = smem_u32(sm);

    const int h = blockIdx.y;
    const int q0 = blockIdx.x * 128;
    const int tid = threadIdx.x;
    const int lane = tid & 31;
    const int w = tid >> 5;
    const int wrow = w * 16;
    const int r4 = lane >> 2;
    const int s2 = (lane & 3) * 2;
    const int vx = tid & 63;
    const int vg = (tid >> 6) * 16;

    // load Q (scaled), split hi/lo into smem
    const float* Qg = g_Q + ((size_t)h * S_LEN + q0) * DK;
#pragma unroll
    for (int i = 0; i < 8; i++) {
        int q = i * 256 + tid;
        int row = q >> 4, c4 = q & 15;
        float4 v = *(const float4*)(Qg + row * DK + c4 * 4);
        v.x *= 0.125f; v.y *= 0.125f; v.z *= 0.125f; v.w *= 0.125f;
        uint2 hh, ll;
        split4(v, hh, ll);
        *(uint2*)&sm[AQ_HI + row * GSTR + c4 * 4] = hh;
        *(uint2*)&sm[AQ_LO + row * GSTR + c4 * 4] = ll;
    }

    // preload tile 0
    const float* Kg = g_K + (size_t)h * S_LEN * DK;
    const float* Vg = g_V + (size_t)h * S_LEN * DK;
    float4 rk[4];
    float rv[16];
#pragma unroll
    for (int i = 0; i < 4; i++) {
        int q = i * 256 + tid;
        int row = q >> 4, c4 = q & 15;
        rk[i] = *(const float4*)(Kg + row * DK + c4 * 4);
    }
#pragma unroll
    for (int j = 0; j < 16; j++) rv[j] = Vg[(vg + j) * DK + vx];
    attn_store_tile(sm + AKV_BASE, rk, rv, tid, vx, vg);
    __syncthreads();

    // hoist Q fragments (tile-invariant)
    uint32_t qh[4][4], ql[4][4];
    {
        uint32_t ao = A_LANE_OFF(lane, wrow, GSTR);
#pragma unroll
        for (int kki = 0; kki < 4; kki++) {
            ldsm_x4(qh[kki], sbase + AQ_HI * 2 + ao + kki * 32);
            ldsm_x4(ql[kki], sbase + AQ_LO * 2 + ao + kki * 32);
        }
    }

    float accO[8][4];
#pragma unroll
    for (int nt = 0; nt < 8; nt++)
#pragma unroll
        for (int i = 0; i < 4; i++) accO[nt][i] = 0.0f;
    float m0r = -1e30f, m1r = -1e30f, l0r = 0.0f, l1r = 0.0f;

    for (int t = 0; t < S_LEN / 64; t++) {
        const int buf = t & 1;
        const uint32_t bb = sbase + (AKV_BASE + buf * AKV_ELEMS) * 2;

        if (t + 1 < S_LEN / 64) {
            const float* Kg2 = Kg + (size_t)(t + 1) * 64 * DK;
            const float* Vg2 = Vg + (size_t)(t + 1) * 64 * DK;
#pragma unroll
            for (int i = 0; i < 4; i++) {
                int q = i * 256 + tid;
                int row = q >> 4, c4 = q & 15;
                rk[i] = *(const float4*)(Kg2 + row * DK + c4 * 4);
            }
#pragma unroll
            for (int j = 0; j < 16; j++) rv[j] = Vg2[(vg + j) * DK + vx];
        }

        // ---- S = Q K^T ----
        float cs[8][4];
#pragma unroll
        for (int nt = 0; nt < 8; nt++)
#pragma unroll
            for (int i = 0; i < 4; i++) cs[nt][i] = 0.0f;

#pragma unroll
        for (int kki = 0; kki < 4; kki++) {
#pragma unroll
            for (int np = 0; np < 4; np++) {
                uint32_t bo = B_LANE_OFF(lane, np * 16, GSTR) + kki * 32;
                uint32_t kbh[4], kbl[4];
                ldsm_x4(kbh, bb + AB_KHI * 2 + bo);
                ldsm_x4(kbl, bb + AB_KLO * 2 + bo);
#pragma unroll
                for (int half = 0; half < 2; half++) {
                    int nt = np * 2 + half;
                    mma_bf16(cs[nt], qh[kki], kbh[half * 2], kbh[half * 2 + 1]);
                    mma_bf16(cs[nt], qh[kki], kbl[half * 2], kbl[half * 2 + 1]);
                    mma_bf16(cs[nt], ql[kki], kbh[half * 2], kbh[half * 2 + 1]);
                }
            }
        }

        // ---- online softmax ----
        float mx0 = -1e30f, mx1 = -1e30f;
#pragma unroll
        for (int nt = 0; nt < 8; nt++) {
            mx0 = fmaxf(mx0, fmaxf(cs[nt][0], cs[nt][1]));
            mx1 = fmaxf(mx1, fmaxf(cs[nt][2], cs[nt][3]));
        }
        mx0 = fmaxf(mx0, __shfl_xor_sync(0xffffffffu, mx0, 1));
        mx0 = fmaxf(mx0, __shfl_xor_sync(0xffffffffu, mx0, 2));
        mx1 = fmaxf(mx1, __shfl_xor_sync(0xffffffffu, mx1, 1));
        mx1 = fmaxf(mx1, __shfl_xor_sync(0xffffffffu, mx1, 2));
        float mn0 = fmaxf(m0r, mx0), mn1 = fmaxf(m1r, mx1);
        float a0 = __expf(m0r - mn0), a1 = __expf(m1r - mn1);
        float sum0 = 0.0f, sum1 = 0.0f;
#pragma unroll
        for (int nt = 0; nt < 8; nt++) {
            cs[nt][0] = __expf(cs[nt][0] - mn0);
            cs[nt][1] = __expf(cs[nt][1] - mn0);
            cs[nt][2] = __expf(cs[nt][2] - mn1);
            cs[nt][3] = __expf(cs[nt][3] - mn1);
            sum0 += cs[nt][0] + cs[nt][1];
            sum1 += cs[nt][2] + cs[nt][3];
        }
        sum0 += __shfl_xor_sync(0xffffffffu, sum0, 1);
        sum0 += __shfl_xor_sync(0xffffffffu, sum0, 2);
        sum1 += __shfl_xor_sync(0xffffffffu, sum1, 1);
        sum1 += __shfl_xor_sync(0xffffffffu, sum1, 2);
        l0r = l0r * a0 + sum0;
        l1r = l1r * a1 + sum1;
        m0r = mn0; m1r = mn1;
#pragma unroll
        for (int nt = 0; nt < 8; nt++) {
            accO[nt][0] *= a0; accO[nt][1] *= a0;
            accO[nt][2] *= a1; accO[nt][3] *= a1;
        }

        // pack P fragments (C-layout == A-layout)
        uint32_t ph[4][4], pl[4][4];
#pragma unroll
        for (int ktk = 0; ktk < 4; ktk++) {
            float p0 = cs[2 * ktk][0], p1 = cs[2 * ktk][1];
            float p2 = cs[2 * ktk][2], p3 = cs[2 * ktk][3];
            float p4 = cs[2 * ktk + 1][0], p5 = cs[2 * ktk + 1][1];
            float p6 = cs[2 * ktk + 1][2], p7 = cs[2 * ktk + 1][3];
            ph[ktk][0] = pack_bf16(p1, p0);
            ph[ktk][1] = pack_bf16(p3, p2);
            ph[ktk][2] = pack_bf16(p5, p4);
            ph[ktk][3] = pack_bf16(p7, p6);
            pl[ktk][0] = pack_bf16(p1 - hi_f(ph[ktk][0]), p0 - lo_f(ph[ktk][0]));
            pl[ktk][1] = pack_bf16(p3 - hi_f(ph[ktk][1]), p2 - lo_f(ph[ktk][1]));
            pl[ktk][2] = pack_bf16(p5 - hi_f(ph[ktk][2]), p4 - lo_f(ph[ktk][2]));
            pl[ktk][3] = pack_bf16(p7 - hi_f(ph[ktk][3]), p6 - lo_f(ph[ktk][3]));
        }

        // ---- O += P V ----
#pragma unroll
        for (int np = 0; np < 4; np++) {
#pragma unroll
            for (int ktk = 0; ktk < 4; ktk++) {
                uint32_t bo = B_LANE_OFF(lane, np * 16, VSTR) + ktk * 32;
                uint32_t vbh[4], vbl[4];
                ldsm_x4(vbh, bb + AB_VHI * 2 + bo);
                ldsm_x4(vbl, bb + AB_VLO * 2 + bo);
#pragma unroll
                for (int half = 0; half < 2; half++) {
                    int nt = np * 2 + half;
                    mma_bf16(accO[nt], ph[ktk], vbh[half * 2], vbh[half * 2 + 1]);
                    mma_bf16(accO[nt], ph[ktk], vbl[half * 2], vbl[half * 2 + 1]);
                    mma_bf16(accO[nt], pl[ktk], vbh[half * 2], vbh[half * 2 + 1]);
                }
            }
        }

        if (t + 1 < S_LEN / 64)
            attn_store_tile(sm + AKV_BASE + (buf ^ 1) * AKV_ELEMS, rk, rv, tid, vx, vg);
        __syncthreads();
    }

    // epilogue
    float inv0 = 1.0f / l0r, inv1 = 1.0f / l1r;
    int row = q0 + wrow + r4;
#pragma unroll
    for (int nt = 0; nt < 8; nt++) {
        float* o0 = g_attn + (size_t)row * DMODEL + h * DK + nt * 8 + s2;
        *(float2*)o0 = make_float2(accO[nt][0] * inv0, accO[nt][1] * inv0);
        *(float2*)(o0 + 8 * DMODEL) = make_float2(accO[nt][2] * inv1, accO[nt][3] * inv1);
    }
}

// ---------------------------------------------------------------------------
extern "C" void kernel_launch(void* const* d_in, const int* in_sizes, int n_in,
                              void* d_out, int out_size)
{
    (void)in_sizes; (void)n_in; (void)out_size;
    const float* q  = (const float*)d_in[0];
    const float* k  = (const float*)d_in[1];
    const float* v  = (const float*)d_in[2];
    const float* Wq = (const float*)d_in[3];
    const float* bq = (const float*)d_in[4];
    const float* Wk = (const float*)d_in[5];
    const float* bk = (const float*)d_in[6];
    const float* Wv = (const float*)d_in[7];
    const float* bv = (const float*)d_in[8];
    const float* Wo = (const float*)d_in[9];
    const float* bo = (const float*)d_in[10];
    float* out = (float*)d_out;

    cudaFuncSetAttribute(qkv_tensor_kernel,
                         cudaFuncAttributeMaxDynamicSharedMemorySize, GEMM_SMEM);
    cudaFuncSetAttribute(out_tensor_kernel,
                         cudaFuncAttributeMaxDynamicSharedMemorySize, GEMM_SMEM);
    cudaFuncSetAttribute(attn_mma_kernel,
                         cudaFuncAttributeMaxDynamicSharedMemorySize, ATTN_SMEM);

    dim3 gqkv(DMODEL / 128, S_LEN / 128, 3);
    qkv_tensor_kernel<<<gqkv, 256, GEMM_SMEM>>>(q, k, v, Wq, Wk, Wv, bq, bk, bv);

    dim3 gattn(S_LEN / 128, NHEAD);
    attn_mma_kernel<<<gattn, 256, ATTN_SMEM>>>();

    dim3 gout(DMODEL / 128, S_LEN / 128);
    out_tensor_kernel<<<gout, 256, GEMM_SMEM>>>(Wo, bo, out);
}

// round 6
// speedup vs baseline: 3.3545x; 1.1497x over previous
#include <cuda_runtime.h>
#include <cuda_bf16.h>
#include <math.h>
#include <stdint.h>

// ---------------------------------------------------------------------------
// MultiHeadAttention: B=1, S=4096, D_MODEL=1024, H=16, d_k=64, fp32.
// All GEMMs on tensor cores (mma.sync m16n8k16 bf16, bf16x3 compensation).
// R5: 512-thread CTAs (16 warps/SM) for both GEMM and attention;
//     attention Q-tile 256; register diet to fit the RF at 16 warps.
// ---------------------------------------------------------------------------

#define S_LEN 4096
#define DMODEL 1024
#define NHEAD 16
#define DK 64

__device__ float g_Q[NHEAD * S_LEN * DK];
__device__ float g_K[NHEAD * S_LEN * DK];
__device__ float g_V[NHEAD * S_LEN * DK];
__device__ float g_attn[S_LEN * DMODEL];

// ============================ helpers ======================================
__device__ __forceinline__ uint32_t smem_u32(const void* p) {
    uint32_t a;
    asm("{ .reg .u64 t; cvta.to.shared.u64 t, %1; cvt.u32.u64 %0, t; }"
        : "=r"(a) : "l"(p));
    return a;
}

__device__ __forceinline__ void mma_bf16(float c[4], const uint32_t a[4],
                                         const uint32_t b0, const uint32_t b1) {
    asm volatile(
        "mma.sync.aligned.m16n8k16.row.col.f32.bf16.bf16.f32 "
        "{%0,%1,%2,%3}, {%4,%5,%6,%7}, {%8,%9}, {%0,%1,%2,%3};"
        : "+f"(c[0]), "+f"(c[1]), "+f"(c[2]), "+f"(c[3])
        : "r"(a[0]), "r"(a[1]), "r"(a[2]), "r"(a[3]), "r"(b0), "r"(b1));
}

__device__ __forceinline__ void ldsm_x4(uint32_t r[4], uint32_t addr) {
    asm volatile("ldmatrix.sync.aligned.m8n8.x4.shared.b16 {%0,%1,%2,%3}, [%4];"
                 : "=r"(r[0]), "=r"(r[1]), "=r"(r[2]), "=r"(r[3]) : "r"(addr));
}

__device__ __forceinline__ uint32_t pack_bf16(float hi, float lo) {
    uint32_t r;
    asm("cvt.rn.bf16x2.f32 %0, %1, %2;" : "=r"(r) : "f"(hi), "f"(lo));
    return r;
}
__device__ __forceinline__ float lo_f(uint32_t p) { return __uint_as_float(p << 16); }
__device__ __forceinline__ float hi_f(uint32_t p) { return __uint_as_float(p & 0xffff0000u); }

__device__ __forceinline__ void split4(float4 v, uint2& h, uint2& l) {
    h.x = pack_bf16(v.y, v.x);
    h.y = pack_bf16(v.w, v.z);
    l.x = pack_bf16(v.y - hi_f(h.x), v.x - lo_f(h.x));
    l.y = pack_bf16(v.w - hi_f(h.y), v.z - lo_f(h.y));
}

// A-type (16x16) ldmatrix lane byte-offset within a [rows][STR] uint16 array
#define A_LANE_OFF(lane, row_base, STR) \
    ((((row_base) + ((lane) & 15)) * (STR) + (((lane) >> 4) * 8)) * 2)
// B-type x4 (two 8-row n-blocks x 16 k) lane byte-offset
#define B_LANE_OFF(lane, n_base, STR) \
    ((((n_base) + (((lane) >> 4) * 8) + ((lane) & 7)) * (STR) + ((((lane) >> 3) & 1) * 8)) * 2)

#define GSTR 72

// ============================ tensor GEMM ==================================
// Y[m,n] = sum_k X[m,k]*W[n,k] + bias[n]. CTA 128x128, 16 warps of 32x32,
// K chunks of 64, double-buffered, bf16x3. 512 threads.
#define GB_AHI 0
#define GB_ALO (128 * GSTR)
#define GB_BHI (2 * 128 * GSTR)
#define GB_BLO (3 * 128 * GSTR)
#define GB_ELEMS (4 * 128 * GSTR)
#define GEMM_SMEM (2 * GB_ELEMS * 2)          // 147456 B

__device__ __forceinline__ void gemm_store_chunk(
    uint16_t* buf, const float4* ra, const float4* rb, int tid)
{
#pragma unroll
    for (int i = 0; i < 4; i++) {
        int q = i * 512 + tid;
        int row = q >> 4, c4 = q & 15;
        uint2 h, l;
        split4(ra[i], h, l);
        *(uint2*)&buf[GB_AHI + row * GSTR + c4 * 4] = h;
        *(uint2*)&buf[GB_ALO + row * GSTR + c4 * 4] = l;
        split4(rb[i], h, l);
        *(uint2*)&buf[GB_BHI + row * GSTR + c4 * 4] = h;
        *(uint2*)&buf[GB_BLO + row * GSTR + c4 * 4] = l;
    }
}

__device__ __forceinline__ void tensor_gemm(
    const float* __restrict__ X, const float* __restrict__ W,
    const float* __restrict__ bias, float* __restrict__ Y, int scatter)
{
    extern __shared__ __align__(16) uint16_t sm[];
    const uint32_t sbase = smem_u32(sm);

    const int tid = threadIdx.x;
    const int lane = tid & 31;
    const int w = tid >> 5;                  // 0..15
    const int wm = (w >> 2) * 32;            // 4 row groups
    const int wn = (w & 3) * 32;             // 4 col groups
    const int m0 = blockIdx.y * 128;
    const int n0 = blockIdx.x * 128;
    const int r4 = lane >> 2;
    const int s2 = (lane & 3) * 2;

    float c[2][4][4];
#pragma unroll
    for (int mt = 0; mt < 2; mt++)
#pragma unroll
        for (int nt = 0; nt < 4; nt++)
#pragma unroll
            for (int i = 0; i < 4; i++) c[mt][nt][i] = 0.0f;

    float4 ra[4], rb[4];
#pragma unroll
    for (int i = 0; i < 4; i++) {
        int q = i * 512 + tid;
        int row = q >> 4, c4 = q & 15;
        ra[i] = *(const float4*)(X + (size_t)(m0 + row) * DMODEL + c4 * 4);
        rb[i] = *(const float4*)(W + (size_t)(n0 + row) * DMODEL + c4 * 4);
    }
    gemm_store_chunk(sm, ra, rb, tid);
    __syncthreads();

    for (int ch = 0; ch < 16; ch++) {
        const int buf = ch & 1;
        const uint32_t bb = sbase + buf * GB_ELEMS * 2;

        if (ch < 15) {
            const int kt = (ch + 1) * 64;
#pragma unroll
            for (int i = 0; i < 4; i++) {
                int q = i * 512 + tid;
                int row = q >> 4, c4 = q & 15;
                ra[i] = *(const float4*)(X + (size_t)(m0 + row) * DMODEL + kt + c4 * 4);
                rb[i] = *(const float4*)(W + (size_t)(n0 + row) * DMODEL + kt + c4 * 4);
            }
        }

#pragma unroll
        for (int kk = 0; kk < 64; kk += 16) {
            uint32_t ah[2][4], al[2][4], bh[2][4], bl[2][4];
#pragma unroll
            for (int mt = 0; mt < 2; mt++) {
                uint32_t ao = A_LANE_OFF(lane, wm + mt * 16, GSTR) + kk * 2;
                ldsm_x4(ah[mt], bb + GB_AHI * 2 + ao);
                ldsm_x4(al[mt], bb + GB_ALO * 2 + ao);
            }
#pragma unroll
            for (int np = 0; np < 2; np++) {
                uint32_t bo = B_LANE_OFF(lane, wn + np * 16, GSTR) + kk * 2;
                ldsm_x4(bh[np], bb + GB_BHI * 2 + bo);
                ldsm_x4(bl[np], bb + GB_BLO * 2 + bo);
            }
#pragma unroll
            for (int mt = 0; mt < 2; mt++)
#pragma unroll
                for (int np = 0; np < 2; np++)
#pragma unroll
                    for (int half = 0; half < 2; half++) {
                        int nt = np * 2 + half;
                        mma_bf16(c[mt][nt], ah[mt], bh[np][half * 2], bh[np][half * 2 + 1]);
                        mma_bf16(c[mt][nt], ah[mt], bl[np][half * 2], bl[np][half * 2 + 1]);
                        mma_bf16(c[mt][nt], al[mt], bh[np][half * 2], bh[np][half * 2 + 1]);
                    }
        }

        if (ch < 15)
            gemm_store_chunk(sm + (buf ^ 1) * GB_ELEMS, ra, rb, tid);
        __syncthreads();
    }

    // epilogue
#pragma unroll
    for (int mt = 0; mt < 2; mt++) {
        int row = m0 + wm + mt * 16 + r4;
#pragma unroll
        for (int nt = 0; nt < 4; nt++) {
            int col = n0 + wn + nt * 8 + s2;
            float b0 = bias[col], b1 = bias[col + 1];
            float2 v0 = make_float2(c[mt][nt][0] + b0, c[mt][nt][1] + b1);
            float2 v1 = make_float2(c[mt][nt][2] + b0, c[mt][nt][3] + b1);
            if (scatter) {
                float* d0 = Y + ((size_t)(col >> 6) * S_LEN + row) * DK + (col & 63);
                *(float2*)d0 = v0;
                *(float2*)(d0 + 8 * DK) = v1;
            } else {
                float* d0 = Y + (size_t)row * DMODEL + col;
                *(float2*)d0 = v0;
                *(float2*)(d0 + 8 * DMODEL) = v1;
            }
        }
    }
}

__global__ void __launch_bounds__(512)
qkv_tensor_kernel(const float* __restrict__ q_in, const float* __restrict__ k_in,
                  const float* __restrict__ v_in,
                  const float* __restrict__ Wq, const float* __restrict__ Wk,
                  const float* __restrict__ Wv,
                  const float* __restrict__ bq, const float* __restrict__ bk,
                  const float* __restrict__ bv)
{
    const float* Xs[3] = {q_in, k_in, v_in};
    const float* Ws[3] = {Wq, Wk, Wv};
    const float* bs[3] = {bq, bk, bv};
    float* dsts[3] = {g_Q, g_K, g_V};
    int z = blockIdx.z;
    tensor_gemm(Xs[z], Ws[z], bs[z], dsts[z], 1);
}

__global__ void __launch_bounds__(512)
out_tensor_kernel(const float* __restrict__ Wo, const float* __restrict__ bo,
                  float* __restrict__ out)
{
    tensor_gemm(g_attn, Wo, bo, out, 0);
}

// ============================ attention ====================================
// CTA = 256 q-rows x 1 head, 16 warps x 16 rows, 64-key tiles, double-buffered.
#define VSTR 72
#define AQ_HI 0
#define AQ_LO (256 * GSTR)
#define AKV_BASE (2 * 256 * GSTR)
#define AB_KHI 0
#define AB_KLO (64 * GSTR)
#define AB_VHI (2 * 64 * GSTR)
#define AB_VLO (2 * 64 * GSTR + 64 * VSTR)
#define AKV_ELEMS (2 * 64 * GSTR + 2 * 64 * VSTR)
#define ATTN_SMEM ((AKV_BASE + 2 * AKV_ELEMS) * 2)    // 147456 B

__device__ __forceinline__ void attn_store_tile(
    uint16_t* buf, const float4* rk, const float* rv, int tid, int vx, int vg)
{
#pragma unroll
    for (int i = 0; i < 2; i++) {
        int q = i * 512 + tid;
        int row = q >> 4, c4 = q & 15;
        uint2 hh, ll;
        split4(rk[i], hh, ll);
        *(uint2*)&buf[AB_KHI + row * GSTR + c4 * 4] = hh;
        *(uint2*)&buf[AB_KLO + row * GSTR + c4 * 4] = ll;
    }
#pragma unroll
    for (int j = 0; j < 8; j++) {
        uint32_t ph = pack_bf16(0.0f, rv[j]);
        float fh = lo_f(ph);
        uint32_t pl = pack_bf16(0.0f, rv[j] - fh);
        buf[AB_VHI + vx * VSTR + vg + j] = (uint16_t)(ph & 0xffffu);
        buf[AB_VLO + vx * VSTR + vg + j] = (uint16_t)(pl & 0xffffu);
    }
}

__global__ void __launch_bounds__(512)
attn_mma_kernel()
{
    extern __shared__ __align__(16) uint16_t sm[];
    const uint32_t sbase = smem_u32(sm);

    const int h = blockIdx.y;
    const int q0 = blockIdx.x * 256;
    const int tid = threadIdx.x;
    const int lane = tid & 31;
    const int w = tid >> 5;          // 0..15
    const int wrow = w * 16;
    const int r4 = lane >> 2;
    const int s2 = (lane & 3) * 2;
    const int vx = tid & 63;         // d index
    const int vg = (tid >> 6) * 8;   // key group base (8 keys/thread)

    // load Q (scaled), split hi/lo into smem
    const float* Qg = g_Q + ((size_t)h * S_LEN + q0) * DK;
#pragma unroll
    for (int i = 0; i < 8; i++) {
        int q = i * 512 + tid;
        int row = q >> 4, c4 = q & 15;
        float4 v = *(const float4*)(Qg + row * DK + c4 * 4);
        v.x *= 0.125f; v.y *= 0.125f; v.z *= 0.125f; v.w *= 0.125f;
        uint2 hh, ll;
        split4(v, hh, ll);
        *(uint2*)&sm[AQ_HI + row * GSTR + c4 * 4] = hh;
        *(uint2*)&sm[AQ_LO + row * GSTR + c4 * 4] = ll;
    }

    // preload tile 0
    const float* Kg = g_K + (size_t)h * S_LEN * DK;
    const float* Vg = g_V + (size_t)h * S_LEN * DK;
    float4 rk[2];
    float rv[8];
#pragma unroll
    for (int i = 0; i < 2; i++) {
        int q = i * 512 + tid;
        int row = q >> 4, c4 = q & 15;
        rk[i] = *(const float4*)(Kg + row * DK + c4 * 4);
    }
#pragma unroll
    for (int j = 0; j < 8; j++) rv[j] = Vg[(vg + j) * DK + vx];
    attn_store_tile(sm + AKV_BASE, rk, rv, tid, vx, vg);
    __syncthreads();

    float accO[8][4];
#pragma unroll
    for (int nt = 0; nt < 8; nt++)
#pragma unroll
        for (int i = 0; i < 4; i++) accO[nt][i] = 0.0f;
    float m0r = -1e30f, m1r = -1e30f, l0r = 0.0f, l1r = 0.0f;

    const uint32_t q_ao = A_LANE_OFF(lane, wrow, GSTR);

    for (int t = 0; t < S_LEN / 64; t++) {
        const int buf = t & 1;
        const uint32_t bb = sbase + (AKV_BASE + buf * AKV_ELEMS) * 2;

        if (t + 1 < S_LEN / 64) {
            const float* Kg2 = Kg + (size_t)(t + 1) * 64 * DK;
            const float* Vg2 = Vg + (size_t)(t + 1) * 64 * DK;
#pragma unroll
            for (int i = 0; i < 2; i++) {
                int q = i * 512 + tid;
                int row = q >> 4, c4 = q & 15;
                rk[i] = *(const float4*)(Kg2 + row * DK + c4 * 4);
            }
#pragma unroll
            for (int j = 0; j < 8; j++) rv[j] = Vg2[(vg + j) * DK + vx];
        }

        // ---- S = Q K^T ----
        float cs[8][4];
#pragma unroll
        for (int nt = 0; nt < 8; nt++)
#pragma unroll
            for (int i = 0; i < 4; i++) cs[nt][i] = 0.0f;

#pragma unroll
        for (int kki = 0; kki < 4; kki++) {
            uint32_t qh[4], ql[4];
            ldsm_x4(qh, sbase + AQ_HI * 2 + q_ao + kki * 32);
            ldsm_x4(ql, sbase + AQ_LO * 2 + q_ao + kki * 32);
#pragma unroll
            for (int np = 0; np < 4; np++) {
                uint32_t bo = B_LANE_OFF(lane, np * 16, GSTR) + kki * 32;
                uint32_t kbh[4], kbl[4];
                ldsm_x4(kbh, bb + AB_KHI * 2 + bo);
                ldsm_x4(kbl, bb + AB_KLO * 2 + bo);
#pragma unroll
                for (int half = 0; half < 2; half++) {
                    int nt = np * 2 + half;
                    mma_bf16(cs[nt], qh, kbh[half * 2], kbh[half * 2 + 1]);
                    mma_bf16(cs[nt], qh, kbl[half * 2], kbl[half * 2 + 1]);
                    mma_bf16(cs[nt], ql, kbh[half * 2], kbh[half * 2 + 1]);
                }
            }
        }

        // ---- online softmax ----
        float mx0 = -1e30f, mx1 = -1e30f;
#pragma unroll
        for (int nt = 0; nt < 8; nt++) {
            mx0 = fmaxf(mx0, fmaxf(cs[nt][0], cs[nt][1]));
            mx1 = fmaxf(mx1, fmaxf(cs[nt][2], cs[nt][3]));
        }
        mx0 = fmaxf(mx0, __shfl_xor_sync(0xffffffffu, mx0, 1));
        mx0 = fmaxf(mx0, __shfl_xor_sync(0xffffffffu, mx0, 2));
        mx1 = fmaxf(mx1, __shfl_xor_sync(0xffffffffu, mx1, 1));
        mx1 = fmaxf(mx1, __shfl_xor_sync(0xffffffffu, mx1, 2));
        float mn0 = fmaxf(m0r, mx0), mn1 = fmaxf(m1r, mx1);
        float a0 = __expf(m0r - mn0), a1 = __expf(m1r - mn1);
        float sum0 = 0.0f, sum1 = 0.0f;
#pragma unroll
        for (int nt = 0; nt < 8; nt++) {
            cs[nt][0] = __expf(cs[nt][0] - mn0);
            cs[nt][1] = __expf(cs[nt][1] - mn0);
            cs[nt][2] = __expf(cs[nt][2] - mn1);
            cs[nt][3] = __expf(cs[nt][3] - mn1);
            sum0 += cs[nt][0] + cs[nt][1];
            sum1 += cs[nt][2] + cs[nt][3];
        }
        sum0 += __shfl_xor_sync(0xffffffffu, sum0, 1);
        sum0 += __shfl_xor_sync(0xffffffffu, sum0, 2);
        sum1 += __shfl_xor_sync(0xffffffffu, sum1, 1);
        sum1 += __shfl_xor_sync(0xffffffffu, sum1, 2);
        l0r = l0r * a0 + sum0;
        l1r = l1r * a1 + sum1;
        m0r = mn0; m1r = mn1;
#pragma unroll
        for (int nt = 0; nt < 8; nt++) {
            accO[nt][0] *= a0; accO[nt][1] *= a0;
            accO[nt][2] *= a1; accO[nt][3] *= a1;
        }

        // ---- O += P V (ktk-major so cs dies progressively) ----
#pragma unroll
        for (int ktk = 0; ktk < 4; ktk++) {
            uint32_t ph[4], pl[4];
            float p0 = cs[2 * ktk][0], p1 = cs[2 * ktk][1];
            float p2 = cs[2 * ktk][2], p3 = cs[2 * ktk][3];
            float p4 = cs[2 * ktk + 1][0], p5 = cs[2 * ktk + 1][1];
            float p6 = cs[2 * ktk + 1][2], p7 = cs[2 * ktk + 1][3];
            ph[0] = pack_bf16(p1, p0);
            ph[1] = pack_bf16(p3, p2);
            ph[2] = pack_bf16(p5, p4);
            ph[3] = pack_bf16(p7, p6);
            pl[0] = pack_bf16(p1 - hi_f(ph[0]), p0 - lo_f(ph[0]));
            pl[1] = pack_bf16(p3 - hi_f(ph[1]), p2 - lo_f(ph[1]));
            pl[2] = pack_bf16(p5 - hi_f(ph[2]), p4 - lo_f(ph[2]));
            pl[3] = pack_bf16(p7 - hi_f(ph[3]), p6 - lo_f(ph[3]));
#pragma unroll
            for (int np = 0; np < 4; np++) {
                uint32_t bo = B_LANE_OFF(lane, np * 16, VSTR) + ktk * 32;
                uint32_t vbh[4], vbl[4];
                ldsm_x4(vbh, bb + AB_VHI * 2 + bo);
                ldsm_x4(vbl, bb + AB_VLO * 2 + bo);
#pragma unroll
                for (int half = 0; half < 2; half++) {
                    int nt = np * 2 + half;
                    mma_bf16(accO[nt], ph, vbh[half * 2], vbh[half * 2 + 1]);
                    mma_bf16(accO[nt], ph, vbl[half * 2], vbl[half * 2 + 1]);
                    mma_bf16(accO[nt], pl, vbh[half * 2], vbh[half * 2 + 1]);
                }
            }
        }

        if (t + 1 < S_LEN / 64)
            attn_store_tile(sm + AKV_BASE + (buf ^ 1) * AKV_ELEMS, rk, rv, tid, vx, vg);
        __syncthreads();
    }

    // epilogue
    float inv0 = 1.0f / l0r, inv1 = 1.0f / l1r;
    int row = q0 + wrow + r4;
#pragma unroll
    for (int nt = 0; nt < 8; nt++) {
        float* o0 = g_attn + (size_t)row * DMODEL + h * DK + nt * 8 + s2;
        *(float2*)o0 = make_float2(accO[nt][0] * inv0, accO[nt][1] * inv0);
        *(float2*)(o0 + 8 * DMODEL) = make_float2(accO[nt][2] * inv1, accO[nt][3] * inv1);
    }
}

// ---------------------------------------------------------------------------
extern "C" void kernel_launch(void* const* d_in, const int* in_sizes, int n_in,
                              void* d_out, int out_size)
{
    (void)in_sizes; (void)n_in; (void)out_size;
    const float* q  = (const float*)d_in[0];
    const float* k  = (const float*)d_in[1];
    const float* v  = (const float*)d_in[2];
    const float* Wq = (const float*)d_in[3];
    const float* bq = (const float*)d_in[4];
    const float* Wk = (const float*)d_in[5];
    const float* bk = (const float*)d_in[6];
    const float* Wv = (const float*)d_in[7];
    const float* bv = (const float*)d_in[8];
    const float* Wo = (const float*)d_in[9];
    const float* bo = (const float*)d_in[10];
    float* out = (float*)d_out;

    cudaFuncSetAttribute(qkv_tensor_kernel,
                         cudaFuncAttributeMaxDynamicSharedMemorySize, GEMM_SMEM);
    cudaFuncSetAttribute(out_tensor_kernel,
                         cudaFuncAttributeMaxDynamicSharedMemorySize, GEMM_SMEM);
    cudaFuncSetAttribute(attn_mma_kernel,
                         cudaFuncAttributeMaxDynamicSharedMemorySize, ATTN_SMEM);

    dim3 gqkv(DMODEL / 128, S_LEN / 128, 3);
    qkv_tensor_kernel<<<gqkv, 512, GEMM_SMEM>>>(q, k, v, Wq, Wk, Wv, bq, bk, bv);

    dim3 gattn(S_LEN / 256, NHEAD);
    attn_mma_kernel<<<gattn, 512, ATTN_SMEM>>>();

    dim3 gout(DMODEL / 128, S_LEN / 128);
    out_tensor_kernel<<<gout, 512, GEMM_SMEM>>>(Wo, bo, out);
}